// round 5
// baseline (speedup 1.0000x reference)
#include <cuda_runtime.h>
#include <cuda_fp16.h>
#include <cstdint>

// ---------------------------------------------------------------------------
// Problem constants
// ---------------------------------------------------------------------------
namespace {
constexpr int T_STEPS = 128, BATCH = 512, HID = 512, INP = 512;
constexpr int M_TOT = T_STEPS * BATCH;              // 65536 GEMM rows
constexpr long long BH = (long long)BATCH * HID;    // 262144 sequences

// GEMM tiling
constexpr int BM = 128, BN = 128, BK = 16;
constexpr int CHUNKS = INP / BK;                    // 32
constexpr int PITCH  = 48;                          // 32B data + 16B pad (bank-clean)
constexpr int TILE_B = 128 * PITCH;                 // 6144 B per operand tile
constexpr int STAGE_B = 4 * TILE_B;                 // Ah, Am, Bh, Bm = 24576
constexpr int NSTAGE = 4;
constexpr int SMEM_TOTAL = NSTAGE * STAGE_B;        // 98304 -> 2 CTAs/SM
}

// Static scratch (allowed; no allocs)
__device__ float  g_xp[(size_t)M_TOT * HID];        // xp fp32, 128 MB
__device__ __half g_xh[(size_t)M_TOT * INP];        // x hi split (fp16)
__device__ __half g_xm[(size_t)M_TOT * INP];        // x mid split
__device__ __half g_wh[(size_t)HID * INP];
__device__ __half g_wm[(size_t)HID * INP];

// ---------------------------------------------------------------------------
// PTX helpers
// ---------------------------------------------------------------------------
__device__ __forceinline__ uint32_t smem_u32(const void* p) {
    uint32_t a;
    asm("{ .reg .u64 t; cvta.to.shared.u64 t, %1; cvt.u32.u64 %0, t; }"
        : "=r"(a) : "l"(p));
    return a;
}
__device__ __forceinline__ void ldsm_x4(uint32_t* r, uint32_t addr) {
    asm volatile("ldmatrix.sync.aligned.m8n8.x4.shared.b16 {%0,%1,%2,%3}, [%4];"
                 : "=r"(r[0]), "=r"(r[1]), "=r"(r[2]), "=r"(r[3]) : "r"(addr));
}
__device__ __forceinline__ void mma_f16(float* c, const uint32_t* a,
                                        const uint32_t* b) {
    asm volatile(
        "mma.sync.aligned.m16n8k16.row.col.f32.f16.f16.f32 "
        "{%0,%1,%2,%3}, {%4,%5,%6,%7}, {%8,%9}, {%0,%1,%2,%3};"
        : "+f"(c[0]), "+f"(c[1]), "+f"(c[2]), "+f"(c[3])
        : "r"(a[0]), "r"(a[1]), "r"(a[2]), "r"(a[3]), "r"(b[0]), "r"(b[1]));
}
__device__ __forceinline__ void cp16(uint32_t dst, const void* src) {
    asm volatile("cp.async.cg.shared.global [%0], [%1], 16;"
                 :: "r"(dst), "l"(src) : "memory");
}
__device__ __forceinline__ void cp_commit() {
    asm volatile("cp.async.commit_group;" ::: "memory");
}
__device__ __forceinline__ void cp_wait2() {
    asm volatile("cp.async.wait_group 2;" ::: "memory");
}
__device__ __forceinline__ uint32_t hpack(__half a, __half b) {
    __half2 t(a, b);
    return *reinterpret_cast<uint32_t*>(&t);
}

// ---------------------------------------------------------------------------
// Split pass: fp32 -> (hi, mid) fp16.  is_w selects destination arrays.
// x = h + m with |m| <= 2^-11 |x|; dropped mm term in GEMM is ~2^-22 rel.
// ---------------------------------------------------------------------------
__global__ __launch_bounds__(256)
void split_kernel(const float4* __restrict__ src, int n4, int is_w)
{
    const int i = blockIdx.x * blockDim.x + threadIdx.x;
    if (i >= n4) return;
    const float4 v = src[i];
    const float f[4] = {v.x, v.y, v.z, v.w};
    __half h[4], m[4];
    #pragma unroll
    for (int j = 0; j < 4; ++j) {
        h[j] = __float2half_rn(f[j]);
        m[j] = __float2half_rn(f[j] - __half2float(h[j]));
    }
    uint2* hd = (uint2*)(is_w ? g_wh : g_xh);
    uint2* md = (uint2*)(is_w ? g_wm : g_xm);
    hd[i] = make_uint2(hpack(h[0], h[1]), hpack(h[2], h[3]));
    md[i] = make_uint2(hpack(m[0], m[1]), hpack(m[2], m[3]));
}

// ---------------------------------------------------------------------------
// HMMA GEMM: g_xp[m,n] = sum_k x[m,k]*W[n,k] + bias[n]
// fp32 via 2-word fp16 split, 3 terms: hh + hm + mh
// cp.async 4-stage pipeline, BK=16 chunks, 2 CTAs/SM.
// ---------------------------------------------------------------------------
__global__ __launch_bounds__(256, 2)
void gemm_hmma_kernel(const float* __restrict__ bias)
{
    extern __shared__ char smem[];
    const uint32_t sbase = smem_u32(smem);
    const int tid = threadIdx.x;
    const int wid = tid >> 5;
    const int lid = tid & 31;
    const int n0 = blockIdx.x * BN;
    const int m0 = blockIdx.y * BM;

    const int warp_m = wid & 1;          // 64-row half
    const int warp_n = wid >> 1;         // 32-col slice

    // ldmatrix lane addressing (pitch 48B, conflict-free: 12 words/row, 8 rows
    // hit banks 0,12,24,4,16,28,8,20)
    const int quad = lid >> 3, lrow = lid & 7;
    const uint32_t laneA = (uint32_t)(((quad & 1) * 8 + lrow) * PITCH + (quad >> 1) * 16);
    const uint32_t laneB = (uint32_t)(((quad >> 1) * 8 + lrow) * PITCH + (quad & 1) * 16);

    float acc[4][4][4];
    #pragma unroll
    for (int i = 0; i < 4; ++i)
        #pragma unroll
        for (int j = 0; j < 4; ++j)
            #pragma unroll
            for (int k = 0; k < 4; ++k) acc[i][j][k] = 0.f;

    // stage fill: tiles {0:Ah, 1:Am, 2:Bh, 3:Bm}; 1024 x 16B chunks, 4/thread
    auto issue_stage = [&](int c) {
        const int kt = c * BK;
        const uint32_t sdst = sbase + (uint32_t)((c & 3) * STAGE_B);
        #pragma unroll
        for (int i = 0; i < 4; ++i) {
            const int q    = i * 256 + tid;
            const int tile = q >> 8;           // compile-time per i
            const int t    = q & 255;
            const int row  = t >> 1;
            const int cc   = t & 1;
            const __half* src;
            if      (tile == 0) src = g_xh + (size_t)(m0 + row) * INP + kt + cc * 8;
            else if (tile == 1) src = g_xm + (size_t)(m0 + row) * INP + kt + cc * 8;
            else if (tile == 2) src = g_wh + (size_t)(n0 + row) * INP + kt + cc * 8;
            else                src = g_wm + (size_t)(n0 + row) * INP + kt + cc * 8;
            cp16(sdst + (uint32_t)(tile * TILE_B + row * PITCH + cc * 16), src);
        }
        cp_commit();
    };

    issue_stage(0);
    issue_stage(1);
    issue_stage(2);

    for (int c = 0; c < CHUNKS; ++c) {
        cp_wait2();
        __syncthreads();

        const uint32_t stg = sbase + (uint32_t)((c & 3) * STAGE_B);
        const uint32_t aB  = stg + (uint32_t)(warp_m * 64 * PITCH) + laneA;
        const uint32_t bB  = stg + (uint32_t)(warp_n * 32 * PITCH) + laneB;

        uint32_t afr[4][4], bfh[4][2], bfm[4][2];

        // B fragments, both splits (tiles 2,3)
        #pragma unroll
        for (int bp = 0; bp < 2; ++bp) {
            uint32_t r4[4];
            ldsm_x4(r4, bB + (uint32_t)(2 * TILE_B + bp * 16 * PITCH));
            bfh[bp * 2 + 0][0] = r4[0]; bfh[bp * 2 + 0][1] = r4[1];
            bfh[bp * 2 + 1][0] = r4[2]; bfh[bp * 2 + 1][1] = r4[3];
            ldsm_x4(r4, bB + (uint32_t)(3 * TILE_B + bp * 16 * PITCH));
            bfm[bp * 2 + 0][0] = r4[0]; bfm[bp * 2 + 0][1] = r4[1];
            bfm[bp * 2 + 1][0] = r4[2]; bfm[bp * 2 + 1][1] = r4[3];
        }

        // A-hi fragments (tile 0): hh + hm
        #pragma unroll
        for (int mt = 0; mt < 4; ++mt)
            ldsm_x4(afr[mt], aB + (uint32_t)(0 * TILE_B + mt * 16 * PITCH));
        #pragma unroll
        for (int mt = 0; mt < 4; ++mt)
            #pragma unroll
            for (int nt = 0; nt < 4; ++nt)
                mma_f16(acc[mt][nt], afr[mt], bfh[nt]);
        #pragma unroll
        for (int mt = 0; mt < 4; ++mt)
            #pragma unroll
            for (int nt = 0; nt < 4; ++nt)
                mma_f16(acc[mt][nt], afr[mt], bfm[nt]);

        // A-mid fragments (tile 1): mh
        #pragma unroll
        for (int mt = 0; mt < 4; ++mt)
            ldsm_x4(afr[mt], aB + (uint32_t)(1 * TILE_B + mt * 16 * PITCH));
        #pragma unroll
        for (int mt = 0; mt < 4; ++mt)
            #pragma unroll
            for (int nt = 0; nt < 4; ++nt)
                mma_f16(acc[mt][nt], afr[mt], bfh[nt]);

        if (c + 3 < CHUNKS) issue_stage(c + 3);
        else                cp_commit();    // empty group keeps wait arithmetic exact
    }

    // ---- epilogue: +bias, store fp32 ----
    const int tr = lid >> 2;
    const int tc = (lid & 3) * 2;
    #pragma unroll
    for (int nt = 0; nt < 4; ++nt) {
        const int col = n0 + warp_n * 32 + nt * 8 + tc;
        const float2 bb = *(const float2*)(bias + col);
        #pragma unroll
        for (int mt = 0; mt < 4; ++mt) {
            const int row = m0 + warp_m * 64 + mt * 16 + tr;
            float2 o0, o1;
            o0.x = acc[mt][nt][0] + bb.x; o0.y = acc[mt][nt][1] + bb.y;
            o1.x = acc[mt][nt][2] + bb.x; o1.y = acc[mt][nt][3] + bb.y;
            *(float2*)(g_xp + (size_t)row * HID + col)       = o0;
            *(float2*)(g_xp + (size_t)(row + 8) * HID + col) = o1;
        }
    }
}

// ---------------------------------------------------------------------------
// Recurrent LIF scan: one thread per (b,h), loops over T. Exact reference math.
// (Reverted to the measured-122us round-3 version.)
// ---------------------------------------------------------------------------
__global__ __launch_bounds__(256)
void lif_scan_kernel(float* __restrict__ out, float* __restrict__ states)
{
    const long long idx = (long long)blockIdx.x * blockDim.x + threadIdx.x;

    float v[4]  = {0.f, 0.f, 0.f, 0.f};
    float av[4] = {0.f, 0.f, 0.f, 0.f};

    const float* px = g_xp + idx;
    float*       po = out  + idx;

    for (int t = 0; t < T_STEPS; ++t) {
        float y  = px[(size_t)t * BH];
        float sc = 0.f;
        #pragma unroll
        for (int l = 0; l < 4; ++l) {
            float vv   = v[l];
            float accv = 0.f;
            float accs = 0.f;
            #pragma unroll
            for (int s = 0; s < 4; ++s) {
                vv = vv + (y - vv) * 0.5f;             // charge
                float sp = (vv >= 1.0f) ? 1.0f : 0.0f; // fire
                vv = vv - sp;                           // soft reset
                accv += vv;
                accs += sp;
            }
            v[l]  = vv;
            y     = accv * 0.25f;
            av[l] = y;
            sc    = accs * 0.25f;
        }
        po[(size_t)t * BH] = sc;
    }

    #pragma unroll
    for (int l = 0; l < 4; ++l)
        states[(size_t)l * BH + idx] = av[l];
}

// ---------------------------------------------------------------------------
// Launch
// ---------------------------------------------------------------------------
extern "C" void kernel_launch(void* const* d_in, const int* in_sizes, int n_in,
                              void* d_out, int out_size)
{
    const float* x = (const float*)d_in[0];   // [T, B, INP]
    const float* W = (const float*)d_in[1];   // [HID, INP]
    const float* b = (const float*)d_in[2];   // [HID]

    float* out    = (float*)d_out;                    // [T, B, H]
    float* states = out + (size_t)T_STEPS * BH;       // [4, B, H]

    // 1) split fp32 -> fp16 hi/mid
    const int nx4 = (int)((size_t)M_TOT * INP / 4);   // 8388608
    const int nw4 = HID * INP / 4;                    // 65536
    split_kernel<<<nx4 / 256, 256>>>((const float4*)x, nx4, 0);
    split_kernel<<<nw4 / 256, 256>>>((const float4*)W, nw4, 1);

    // 2) tensor-core projection GEMM
    cudaFuncSetAttribute(gemm_hmma_kernel,
                         cudaFuncAttributeMaxDynamicSharedMemorySize, SMEM_TOTAL);
    dim3 gemm_grid(HID / BN, M_TOT / BM);             // (4, 512)
    gemm_hmma_kernel<<<gemm_grid, 256, SMEM_TOTAL>>>(b);

    // 3) recurrent scan
    lif_scan_kernel<<<(unsigned)(BH / 256), 256>>>(out, states);
}

// round 6
// speedup vs baseline: 1.6835x; 1.6835x over previous
#include <cuda_runtime.h>
#include <cuda_fp16.h>
#include <cstdint>

// ---------------------------------------------------------------------------
// Problem constants
// ---------------------------------------------------------------------------
namespace {
constexpr int T_STEPS = 128, BATCH = 512, HID = 512, INP = 512;
constexpr int M_TOT = T_STEPS * BATCH;              // 65536 GEMM rows
constexpr long long BH = (long long)BATCH * HID;    // 262144 sequences

// GEMM tiling
constexpr int BM = 128, BN = 128, BK = 16;
constexpr int CHUNKS = INP / BK;                    // 32
constexpr int PITCH  = 48;                          // 32B data + 16B pad (bank-clean)
constexpr int TILE_B = 128 * PITCH;                 // 6144 B per operand tile
constexpr int STAGE_B = 4 * TILE_B;                 // Ah, Am, Bh, Bm = 24576
constexpr int NSTAGE = 4;
constexpr int SMEM_TOTAL = NSTAGE * STAGE_B;        // 98304 -> 2 CTAs/SM
}

// Static scratch (allowed; no allocs)
__device__ float  g_xp[(size_t)M_TOT * HID];        // xp fp32, 128 MB
__device__ __half g_xh[(size_t)M_TOT * INP];        // x hi split (fp16)
__device__ __half g_xm[(size_t)M_TOT * INP];        // x mid split
__device__ __half g_wh[(size_t)HID * INP];
__device__ __half g_wm[(size_t)HID * INP];

// ---------------------------------------------------------------------------
// PTX helpers
// ---------------------------------------------------------------------------
__device__ __forceinline__ uint32_t smem_u32(const void* p) {
    uint32_t a;
    asm("{ .reg .u64 t; cvta.to.shared.u64 t, %1; cvt.u32.u64 %0, t; }"
        : "=r"(a) : "l"(p));
    return a;
}
__device__ __forceinline__ void ldsm_x4(uint32_t* r, uint32_t addr) {
    asm volatile("ldmatrix.sync.aligned.m8n8.x4.shared.b16 {%0,%1,%2,%3}, [%4];"
                 : "=r"(r[0]), "=r"(r[1]), "=r"(r[2]), "=r"(r[3]) : "r"(addr));
}
__device__ __forceinline__ void mma_f16(float* c, const uint32_t* a,
                                        const uint32_t* b) {
    asm volatile(
        "mma.sync.aligned.m16n8k16.row.col.f32.f16.f16.f32 "
        "{%0,%1,%2,%3}, {%4,%5,%6,%7}, {%8,%9}, {%0,%1,%2,%3};"
        : "+f"(c[0]), "+f"(c[1]), "+f"(c[2]), "+f"(c[3])
        : "r"(a[0]), "r"(a[1]), "r"(a[2]), "r"(a[3]), "r"(b[0]), "r"(b[1]));
}
__device__ __forceinline__ void cp16(uint32_t dst, const void* src) {
    asm volatile("cp.async.cg.shared.global [%0], [%1], 16;"
                 :: "r"(dst), "l"(src) : "memory");
}
__device__ __forceinline__ void cp_commit() {
    asm volatile("cp.async.commit_group;" ::: "memory");
}
__device__ __forceinline__ void cp_wait2() {
    asm volatile("cp.async.wait_group 2;" ::: "memory");
}
__device__ __forceinline__ uint32_t hpack(__half a, __half b) {
    __half2 t(a, b);
    return *reinterpret_cast<uint32_t*>(&t);
}

// ---------------------------------------------------------------------------
// Split pass: fp32 -> (hi, mid) fp16.  4x float4 per thread, uint4 stores.
// ---------------------------------------------------------------------------
__global__ __launch_bounds__(256)
void split_kernel(const float4* __restrict__ src, int n4, int is_w)
{
    const int i = (blockIdx.x * blockDim.x + threadIdx.x) * 4;  // 4 float4 groups
    if (i + 3 >= n4 + 3 && i >= n4) return;   // n4 % 4 == 0 in practice

    float4 v[4];
    #pragma unroll
    for (int g = 0; g < 4; ++g) v[g] = src[i + g];   // 64B read, MLP 4

    uint32_t hp[8], mp[8];
    #pragma unroll
    for (int g = 0; g < 4; ++g) {
        const float f[4] = {v[g].x, v[g].y, v[g].z, v[g].w};
        __half h[4], m[4];
        #pragma unroll
        for (int j = 0; j < 4; ++j) {
            h[j] = __float2half_rn(f[j]);
            m[j] = __float2half_rn(f[j] - __half2float(h[j]));
        }
        hp[g * 2 + 0] = hpack(h[0], h[1]); hp[g * 2 + 1] = hpack(h[2], h[3]);
        mp[g * 2 + 0] = hpack(m[0], m[1]); mp[g * 2 + 1] = hpack(m[2], m[3]);
    }
    uint4* hd = (uint4*)(is_w ? g_wh : g_xh);
    uint4* md = (uint4*)(is_w ? g_wm : g_xm);
    const int o = i / 2;                       // uint4 = 2 float4-groups of halves
    hd[o + 0] = make_uint4(hp[0], hp[1], hp[2], hp[3]);
    hd[o + 1] = make_uint4(hp[4], hp[5], hp[6], hp[7]);
    md[o + 0] = make_uint4(mp[0], mp[1], mp[2], mp[3]);
    md[o + 1] = make_uint4(mp[4], mp[5], mp[6], mp[7]);
}

// ---------------------------------------------------------------------------
// HMMA GEMM: g_xp[m,n] = sum_k x[m,k]*W[n,k] + bias[n]
// fp32 via 2-word fp16 split, 3 terms: hh + hm + mh
// cp.async 4-stage pipeline, BK=16 chunks, 2 CTAs/SM.
// ---------------------------------------------------------------------------
__global__ __launch_bounds__(256, 2)
void gemm_hmma_kernel(const float* __restrict__ bias)
{
    extern __shared__ char smem[];
    const uint32_t sbase = smem_u32(smem);
    const int tid = threadIdx.x;
    const int wid = tid >> 5;
    const int lid = tid & 31;
    const int n0 = blockIdx.x * BN;
    const int m0 = blockIdx.y * BM;

    const int warp_m = wid & 1;          // 64-row half
    const int warp_n = wid >> 1;         // 32-col slice

    const int quad = lid >> 3, lrow = lid & 7;
    const uint32_t laneA = (uint32_t)(((quad & 1) * 8 + lrow) * PITCH + (quad >> 1) * 16);
    const uint32_t laneB = (uint32_t)(((quad >> 1) * 8 + lrow) * PITCH + (quad & 1) * 16);

    float acc[4][4][4];
    #pragma unroll
    for (int i = 0; i < 4; ++i)
        #pragma unroll
        for (int j = 0; j < 4; ++j)
            #pragma unroll
            for (int k = 0; k < 4; ++k) acc[i][j][k] = 0.f;

    // stage fill: tiles {0:Ah, 1:Am, 2:Bh, 3:Bm}; 1024 x 16B chunks, 4/thread
    auto issue_stage = [&](int c) {
        const int kt = c * BK;
        const uint32_t sdst = sbase + (uint32_t)((c & 3) * STAGE_B);
        #pragma unroll
        for (int i = 0; i < 4; ++i) {
            const int q    = i * 256 + tid;
            const int tile = q >> 8;
            const int t    = q & 255;
            const int row  = t >> 1;
            const int cc   = t & 1;
            const __half* src;
            if      (tile == 0) src = g_xh + (size_t)(m0 + row) * INP + kt + cc * 8;
            else if (tile == 1) src = g_xm + (size_t)(m0 + row) * INP + kt + cc * 8;
            else if (tile == 2) src = g_wh + (size_t)(n0 + row) * INP + kt + cc * 8;
            else                src = g_wm + (size_t)(n0 + row) * INP + kt + cc * 8;
            cp16(sdst + (uint32_t)(tile * TILE_B + row * PITCH + cc * 16), src);
        }
        cp_commit();
    };

    issue_stage(0);
    issue_stage(1);
    issue_stage(2);

    for (int c = 0; c < CHUNKS; ++c) {
        cp_wait2();
        __syncthreads();

        const uint32_t stg = sbase + (uint32_t)((c & 3) * STAGE_B);
        const uint32_t aB  = stg + (uint32_t)(warp_m * 64 * PITCH) + laneA;
        const uint32_t bB  = stg + (uint32_t)(warp_n * 32 * PITCH) + laneB;

        uint32_t afr[4][4], bfh[4][2], bfm[4][2];

        // B fragments, both splits (tiles 2,3)
        #pragma unroll
        for (int bp = 0; bp < 2; ++bp) {
            uint32_t r4[4];
            ldsm_x4(r4, bB + (uint32_t)(2 * TILE_B + bp * 16 * PITCH));
            bfh[bp * 2 + 0][0] = r4[0]; bfh[bp * 2 + 0][1] = r4[1];
            bfh[bp * 2 + 1][0] = r4[2]; bfh[bp * 2 + 1][1] = r4[3];
            ldsm_x4(r4, bB + (uint32_t)(3 * TILE_B + bp * 16 * PITCH));
            bfm[bp * 2 + 0][0] = r4[0]; bfm[bp * 2 + 0][1] = r4[1];
            bfm[bp * 2 + 1][0] = r4[2]; bfm[bp * 2 + 1][1] = r4[3];
        }
        // A-hi fragments (tile 0)
        #pragma unroll
        for (int mt = 0; mt < 4; ++mt)
            ldsm_x4(afr[mt], aB + (uint32_t)(0 * TILE_B + mt * 16 * PITCH));

        // issue next DMA stage early so it overlaps the MMA block
        if (c + 3 < CHUNKS) issue_stage(c + 3);
        else                cp_commit();

        // hh + hm
        #pragma unroll
        for (int mt = 0; mt < 4; ++mt)
            #pragma unroll
            for (int nt = 0; nt < 4; ++nt)
                mma_f16(acc[mt][nt], afr[mt], bfh[nt]);
        #pragma unroll
        for (int mt = 0; mt < 4; ++mt)
            #pragma unroll
            for (int nt = 0; nt < 4; ++nt)
                mma_f16(acc[mt][nt], afr[mt], bfm[nt]);

        // A-mid fragments (tile 1): mh
        #pragma unroll
        for (int mt = 0; mt < 4; ++mt)
            ldsm_x4(afr[mt], aB + (uint32_t)(1 * TILE_B + mt * 16 * PITCH));
        #pragma unroll
        for (int mt = 0; mt < 4; ++mt)
            #pragma unroll
            for (int nt = 0; nt < 4; ++nt)
                mma_f16(acc[mt][nt], afr[mt], bfh[nt]);
    }

    // ---- epilogue: +bias, store fp32 ----
    const int tr = lid >> 2;
    const int tc = (lid & 3) * 2;
    #pragma unroll
    for (int nt = 0; nt < 4; ++nt) {
        const int col = n0 + warp_n * 32 + nt * 8 + tc;
        const float2 bb = *(const float2*)(bias + col);
        #pragma unroll
        for (int mt = 0; mt < 4; ++mt) {
            const int row = m0 + warp_m * 64 + mt * 16 + tr;
            float2 o0, o1;
            o0.x = acc[mt][nt][0] + bb.x; o0.y = acc[mt][nt][1] + bb.y;
            o1.x = acc[mt][nt][2] + bb.x; o1.y = acc[mt][nt][3] + bb.y;
            *(float2*)(g_xp + (size_t)row * HID + col)       = o0;
            *(float2*)(g_xp + (size_t)(row + 8) * HID + col) = o1;
        }
    }
}

// ---------------------------------------------------------------------------
// Recurrent LIF scan: one thread per (b,h).  t-loop unrolled x4 with batched
// loads (MLP 4).  Charge recurrence as v = fma(v, 0.5, 0.5*y)  (0.5*y exact;
// <=1-ulp divergence vs reference 2-op form).
// ---------------------------------------------------------------------------
__global__ __launch_bounds__(256)
void lif_scan_kernel(float* __restrict__ out, float* __restrict__ states)
{
    const long long idx = (long long)blockIdx.x * blockDim.x + threadIdx.x;

    float v[4]  = {0.f, 0.f, 0.f, 0.f};
    float av[4] = {0.f, 0.f, 0.f, 0.f};

    const float* px = g_xp + idx;
    float*       po = out  + idx;

    #pragma unroll 1
    for (int t = 0; t < T_STEPS; t += 4) {
        float yin[4];
        #pragma unroll
        for (int u = 0; u < 4; ++u)
            yin[u] = px[(size_t)(t + u) * BH];     // 4 loads in flight

        #pragma unroll
        for (int u = 0; u < 4; ++u) {
            float y  = yin[u];
            float sc = 0.f;
            #pragma unroll
            for (int l = 0; l < 4; ++l) {
                const float c = y * 0.5f;           // exact
                float vv   = v[l];
                float accv = 0.f, accs = 0.f;
                #pragma unroll
                for (int s = 0; s < 4; ++s) {
                    vv = __fmaf_rn(vv, 0.5f, c);            // charge
                    const float sp = (vv >= 1.0f) ? 1.0f : 0.0f;
                    vv -= sp;                                // soft reset
                    accv += vv;
                    accs += sp;
                }
                v[l]  = vv;
                y     = accv * 0.25f;
                av[l] = y;
                sc    = accs * 0.25f;
            }
            po[(size_t)(t + u) * BH] = sc;
        }
    }

    #pragma unroll
    for (int l = 0; l < 4; ++l)
        states[(size_t)l * BH + idx] = av[l];
}

// ---------------------------------------------------------------------------
// Launch
// ---------------------------------------------------------------------------
extern "C" void kernel_launch(void* const* d_in, const int* in_sizes, int n_in,
                              void* d_out, int out_size)
{
    const float* x = (const float*)d_in[0];   // [T, B, INP]
    const float* W = (const float*)d_in[1];   // [HID, INP]
    const float* b = (const float*)d_in[2];   // [HID]

    float* out    = (float*)d_out;                    // [T, B, H]
    float* states = out + (size_t)T_STEPS * BH;       // [4, B, H]

    // 1) split fp32 -> fp16 hi/mid
    const int nx4 = (int)((size_t)M_TOT * INP / 4);   // 8388608
    const int nw4 = HID * INP / 4;                    // 65536
    split_kernel<<<nx4 / 4 / 256, 256>>>((const float4*)x, nx4, 0);
    split_kernel<<<nw4 / 4 / 256, 256>>>((const float4*)W, nw4, 1);

    // 2) tensor-core projection GEMM
    cudaFuncSetAttribute(gemm_hmma_kernel,
                         cudaFuncAttributeMaxDynamicSharedMemorySize, SMEM_TOTAL);
    dim3 gemm_grid(HID / BN, M_TOT / BM);             // (4, 512)
    gemm_hmma_kernel<<<gemm_grid, 256, SMEM_TOTAL>>>(b);

    // 3) recurrent scan
    lif_scan_kernel<<<(unsigned)(BH / 256), 256>>>(out, states);
}

// round 7
// speedup vs baseline: 1.7051x; 1.0128x over previous
#include <cuda_runtime.h>
#include <cuda_fp16.h>
#include <cstdint>

// ---------------------------------------------------------------------------
// Problem constants
// ---------------------------------------------------------------------------
namespace {
constexpr int T_STEPS = 128, BATCH = 512, HID = 512, INP = 512;
constexpr int M_TOT = T_STEPS * BATCH;              // 65536 GEMM rows
constexpr long long BH = (long long)BATCH * HID;    // 262144 sequences

// GEMM tiling: CTA 128(M) x 256(N), BK=16, warp tile 64x64
constexpr int BM = 128, BN = 256, BK = 16;
constexpr int CHUNKS = INP / BK;                    // 32
constexpr int PITCH  = 48;                          // 32B data + 16B pad (bank-clean)
constexpr int A_T    = BM * PITCH;                  // 6144  per A split
constexpr int B_T    = BN * PITCH;                  // 12288 per B split
constexpr int OFF_AH = 0;
constexpr int OFF_AM = A_T;                         // 6144
constexpr int OFF_BH = 2 * A_T;                     // 12288
constexpr int OFF_BM = 2 * A_T + B_T;               // 24576
constexpr int STAGE_B = 2 * A_T + 2 * B_T;          // 36864
constexpr int NSTAGE = 4;
constexpr int SMEM_TOTAL = NSTAGE * STAGE_B;        // 147456
}

// Static scratch (allowed; no allocs)
__device__ float  g_xp[(size_t)M_TOT * HID];        // xp fp32, 128 MB
__device__ __half g_xh[(size_t)M_TOT * INP];        // x hi split (fp16)
__device__ __half g_xm[(size_t)M_TOT * INP];        // x mid split
__device__ __half g_wh[(size_t)HID * INP];
__device__ __half g_wm[(size_t)HID * INP];

// ---------------------------------------------------------------------------
// PTX helpers
// ---------------------------------------------------------------------------
__device__ __forceinline__ uint32_t smem_u32(const void* p) {
    uint32_t a;
    asm("{ .reg .u64 t; cvta.to.shared.u64 t, %1; cvt.u32.u64 %0, t; }"
        : "=r"(a) : "l"(p));
    return a;
}
__device__ __forceinline__ void ldsm_x4(uint32_t* r, uint32_t addr) {
    asm volatile("ldmatrix.sync.aligned.m8n8.x4.shared.b16 {%0,%1,%2,%3}, [%4];"
                 : "=r"(r[0]), "=r"(r[1]), "=r"(r[2]), "=r"(r[3]) : "r"(addr));
}
__device__ __forceinline__ void mma_f16(float* c, const uint32_t* a,
                                        const uint32_t* b) {
    asm volatile(
        "mma.sync.aligned.m16n8k16.row.col.f32.f16.f16.f32 "
        "{%0,%1,%2,%3}, {%4,%5,%6,%7}, {%8,%9}, {%0,%1,%2,%3};"
        : "+f"(c[0]), "+f"(c[1]), "+f"(c[2]), "+f"(c[3])
        : "r"(a[0]), "r"(a[1]), "r"(a[2]), "r"(a[3]), "r"(b[0]), "r"(b[1]));
}
__device__ __forceinline__ void cp16(uint32_t dst, const void* src) {
    asm volatile("cp.async.cg.shared.global [%0], [%1], 16;"
                 :: "r"(dst), "l"(src) : "memory");
}
__device__ __forceinline__ void cp_commit() {
    asm volatile("cp.async.commit_group;" ::: "memory");
}
__device__ __forceinline__ void cp_wait2() {
    asm volatile("cp.async.wait_group 2;" ::: "memory");
}
__device__ __forceinline__ uint32_t hpack(__half a, __half b) {
    __half2 t(a, b);
    return *reinterpret_cast<uint32_t*>(&t);
}

// ---------------------------------------------------------------------------
// Split pass: fp32 -> (hi, mid) fp16.  8x float4 per thread (MLP 8).
// ---------------------------------------------------------------------------
__global__ __launch_bounds__(256)
void split_kernel(const float4* __restrict__ src, int n4, int is_w)
{
    const int i = (blockIdx.x * blockDim.x + threadIdx.x) * 8;   // 8 float4 groups
    if (i >= n4) return;                                          // n4 % 8 == 0

    float4 v[8];
    #pragma unroll
    for (int g = 0; g < 8; ++g) v[g] = src[i + g];   // 128B read, MLP 8

    uint32_t hp[16], mp[16];
    #pragma unroll
    for (int g = 0; g < 8; ++g) {
        const float f[4] = {v[g].x, v[g].y, v[g].z, v[g].w};
        __half h[4], m[4];
        #pragma unroll
        for (int j = 0; j < 4; ++j) {
            h[j] = __float2half_rn(f[j]);
            m[j] = __float2half_rn(f[j] - __half2float(h[j]));
        }
        hp[g * 2 + 0] = hpack(h[0], h[1]); hp[g * 2 + 1] = hpack(h[2], h[3]);
        mp[g * 2 + 0] = hpack(m[0], m[1]); mp[g * 2 + 1] = hpack(m[2], m[3]);
    }
    uint4* hd = (uint4*)(is_w ? g_wh : g_xh);
    uint4* md = (uint4*)(is_w ? g_wm : g_xm);
    const int o = i / 2;                       // uint4 = 2 float4-groups of halves
    #pragma unroll
    for (int g = 0; g < 4; ++g) {
        hd[o + g] = make_uint4(hp[4 * g], hp[4 * g + 1], hp[4 * g + 2], hp[4 * g + 3]);
        md[o + g] = make_uint4(mp[4 * g], mp[4 * g + 1], mp[4 * g + 2], mp[4 * g + 3]);
    }
}

// ---------------------------------------------------------------------------
// HMMA GEMM: g_xp[m,n] = sum_k x[m,k]*W[n,k] + bias[n]
// fp32 via 2-word fp16 split, 3 terms: hh + hm + mh
// CTA 128x256, warp tile 64x64, cp.async 4-stage pipeline.
// ---------------------------------------------------------------------------
__global__ __launch_bounds__(256, 1)
void gemm_hmma_kernel(const float* __restrict__ bias)
{
    extern __shared__ char smem[];
    const uint32_t sbase = smem_u32(smem);
    const int tid = threadIdx.x;
    const int wid = tid >> 5;
    const int lid = tid & 31;
    const int n0 = blockIdx.x * BN;
    const int m0 = blockIdx.y * BM;

    const int warp_m = wid & 1;          // 64-row half
    const int warp_n = wid >> 1;         // 64-col slice (4 slices)

    const int quad = lid >> 3, lrow = lid & 7;
    const uint32_t laneA = (uint32_t)(((quad & 1) * 8 + lrow) * PITCH + (quad >> 1) * 16);
    const uint32_t laneB = (uint32_t)(((quad >> 1) * 8 + lrow) * PITCH + (quad & 1) * 16);

    float acc[4][8][4];
    #pragma unroll
    for (int i = 0; i < 4; ++i)
        #pragma unroll
        for (int j = 0; j < 8; ++j)
            #pragma unroll
            for (int k = 0; k < 4; ++k) acc[i][j][k] = 0.f;

    // stage fill: 1536 x 16B chunks, 6/thread
    // i=0: Ah(128r), i=1: Am, i=2..3: Bh(256r), i=4..5: Bm
    auto issue_stage = [&](int c) {
        const int kt = c * BK;
        const uint32_t sdst = sbase + (uint32_t)((c & 3) * STAGE_B);
        #pragma unroll
        for (int i = 0; i < 6; ++i) {
            const int q = i * 256 + tid;
            const __half* src;
            uint32_t dst;
            if (i == 0) {
                const int row = q >> 1, cc = q & 1;
                src = g_xh + (size_t)(m0 + row) * INP + kt + cc * 8;
                dst = (uint32_t)(OFF_AH + row * PITCH + cc * 16);
            } else if (i == 1) {
                const int t = q - 256, row = t >> 1, cc = t & 1;
                src = g_xm + (size_t)(m0 + row) * INP + kt + cc * 8;
                dst = (uint32_t)(OFF_AM + row * PITCH + cc * 16);
            } else if (i < 4) {
                const int t = q - 512, row = t >> 1, cc = t & 1;
                src = g_wh + (size_t)(n0 + row) * INP + kt + cc * 8;
                dst = (uint32_t)(OFF_BH + row * PITCH + cc * 16);
            } else {
                const int t = q - 1024, row = t >> 1, cc = t & 1;
                src = g_wm + (size_t)(n0 + row) * INP + kt + cc * 8;
                dst = (uint32_t)(OFF_BM + row * PITCH + cc * 16);
            }
            cp16(sdst + dst, src);
        }
        cp_commit();
    };

    issue_stage(0);
    issue_stage(1);
    issue_stage(2);

    for (int c = 0; c < CHUNKS; ++c) {
        cp_wait2();
        __syncthreads();

        const uint32_t stg = sbase + (uint32_t)((c & 3) * STAGE_B);
        const uint32_t aB  = stg + (uint32_t)(warp_m * 64 * PITCH) + laneA;
        const uint32_t bB  = stg + (uint32_t)(warp_n * 64 * PITCH) + laneB;

        uint32_t afr[4][4], bfh[8][2], bfm[8][2];

        // B fragments, both splits (4 ldsm_x4 each covering 16 cols)
        #pragma unroll
        for (int bp = 0; bp < 4; ++bp) {
            uint32_t r4[4];
            ldsm_x4(r4, bB + (uint32_t)(OFF_BH + bp * 16 * PITCH));
            bfh[bp * 2 + 0][0] = r4[0]; bfh[bp * 2 + 0][1] = r4[1];
            bfh[bp * 2 + 1][0] = r4[2]; bfh[bp * 2 + 1][1] = r4[3];
            ldsm_x4(r4, bB + (uint32_t)(OFF_BM + bp * 16 * PITCH));
            bfm[bp * 2 + 0][0] = r4[0]; bfm[bp * 2 + 0][1] = r4[1];
            bfm[bp * 2 + 1][0] = r4[2]; bfm[bp * 2 + 1][1] = r4[3];
        }
        // A-hi fragments
        #pragma unroll
        for (int mt = 0; mt < 4; ++mt)
            ldsm_x4(afr[mt], aB + (uint32_t)(OFF_AH + mt * 16 * PITCH));

        // next DMA stage overlaps the MMA block
        if (c + 3 < CHUNKS) issue_stage(c + 3);
        else                cp_commit();

        // hh + hm
        #pragma unroll
        for (int mt = 0; mt < 4; ++mt)
            #pragma unroll
            for (int nt = 0; nt < 8; ++nt)
                mma_f16(acc[mt][nt], afr[mt], bfh[nt]);
        #pragma unroll
        for (int mt = 0; mt < 4; ++mt)
            #pragma unroll
            for (int nt = 0; nt < 8; ++nt)
                mma_f16(acc[mt][nt], afr[mt], bfm[nt]);

        // A-mid fragments: mh
        #pragma unroll
        for (int mt = 0; mt < 4; ++mt)
            ldsm_x4(afr[mt], aB + (uint32_t)(OFF_AM + mt * 16 * PITCH));
        #pragma unroll
        for (int mt = 0; mt < 4; ++mt)
            #pragma unroll
            for (int nt = 0; nt < 8; ++nt)
                mma_f16(acc[mt][nt], afr[mt], bfh[nt]);
    }

    // ---- epilogue: +bias, store fp32 ----
    const int tr = lid >> 2;
    const int tc = (lid & 3) * 2;
    #pragma unroll
    for (int nt = 0; nt < 8; ++nt) {
        const int col = n0 + warp_n * 64 + nt * 8 + tc;
        const float2 bb = *(const float2*)(bias + col);
        #pragma unroll
        for (int mt = 0; mt < 4; ++mt) {
            const int row = m0 + warp_m * 64 + mt * 16 + tr;
            float2 o0, o1;
            o0.x = acc[mt][nt][0] + bb.x; o0.y = acc[mt][nt][1] + bb.y;
            o1.x = acc[mt][nt][2] + bb.x; o1.y = acc[mt][nt][3] + bb.y;
            *(float2*)(g_xp + (size_t)row * HID + col)       = o0;
            *(float2*)(g_xp + (size_t)(row + 8) * HID + col) = o1;
        }
    }
}

// ---------------------------------------------------------------------------
// Recurrent LIF scan: one thread per (b,h).  t-loop unrolled x8 with batched
// loads (MLP 8).  Charge: v = fma(v, 0.5, 0.5*y)  (0.5*y exact).
// ---------------------------------------------------------------------------
__global__ __launch_bounds__(256)
void lif_scan_kernel(float* __restrict__ out, float* __restrict__ states)
{
    const long long idx = (long long)blockIdx.x * blockDim.x + threadIdx.x;

    float v[4]  = {0.f, 0.f, 0.f, 0.f};
    float av[4] = {0.f, 0.f, 0.f, 0.f};

    const float* px = g_xp + idx;
    float*       po = out  + idx;

    #pragma unroll 1
    for (int t = 0; t < T_STEPS; t += 8) {
        float yin[8];
        #pragma unroll
        for (int u = 0; u < 8; ++u)
            yin[u] = px[(size_t)(t + u) * BH];     // 8 loads in flight

        #pragma unroll
        for (int u = 0; u < 8; ++u) {
            float y  = yin[u];
            float sc = 0.f;
            #pragma unroll
            for (int l = 0; l < 4; ++l) {
                const float c = y * 0.5f;           // exact
                float vv   = v[l];
                float accv = 0.f, accs = 0.f;
                #pragma unroll
                for (int s = 0; s < 4; ++s) {
                    vv = __fmaf_rn(vv, 0.5f, c);            // charge
                    const float sp = (vv >= 1.0f) ? 1.0f : 0.0f;
                    vv -= sp;                                // soft reset
                    accv += vv;
                    accs += sp;
                }
                v[l]  = vv;
                y     = accv * 0.25f;
                av[l] = y;
                sc    = accs * 0.25f;
            }
            po[(size_t)(t + u) * BH] = sc;
        }
    }

    #pragma unroll
    for (int l = 0; l < 4; ++l)
        states[(size_t)l * BH + idx] = av[l];
}

// ---------------------------------------------------------------------------
// Launch
// ---------------------------------------------------------------------------
extern "C" void kernel_launch(void* const* d_in, const int* in_sizes, int n_in,
                              void* d_out, int out_size)
{
    const float* x = (const float*)d_in[0];   // [T, B, INP]
    const float* W = (const float*)d_in[1];   // [HID, INP]
    const float* b = (const float*)d_in[2];   // [HID]

    float* out    = (float*)d_out;                    // [T, B, H]
    float* states = out + (size_t)T_STEPS * BH;       // [4, B, H]

    // 1) split fp32 -> fp16 hi/mid
    const int nx4 = (int)((size_t)M_TOT * INP / 4);   // 8388608
    const int nw4 = HID * INP / 4;                    // 65536
    split_kernel<<<nx4 / 8 / 256, 256>>>((const float4*)x, nx4, 0);
    split_kernel<<<nw4 / 8 / 256, 256>>>((const float4*)W, nw4, 1);

    // 2) tensor-core projection GEMM
    cudaFuncSetAttribute(gemm_hmma_kernel,
                         cudaFuncAttributeMaxDynamicSharedMemorySize, SMEM_TOTAL);
    dim3 gemm_grid(HID / BN, M_TOT / BM);             // (2, 512)
    gemm_hmma_kernel<<<gemm_grid, 256, SMEM_TOTAL>>>(b);

    // 3) recurrent scan
    lif_scan_kernel<<<(unsigned)(BH / 256), 256>>>(out, states);
}